// round 4
// baseline (speedup 1.0000x reference)
#include <cuda_runtime.h>
#include <cuda_bf16.h>
#include <math.h>

// Problem constants
#define EMB_DIM 4096
#define INNER   1024
#define VOCAB   32000
#define NPRED   3
#define BATCH   2
#define SEQ     512
#define MTOK    (BATCH * SEQ)        // 1024 token rows
#define INDS_LD (SEQ + NPRED)        // 515

// GEMM tiling
#define BM 128
#define BN 128
#define BK 16
#define AS 132                        // padded smem leading stride (floats)

// Scratch (allowed: __device__ globals, no allocation)
__device__ float g_tmp[MTOK * INNER];   // proj output + alpha*z (pre-activation)
__device__ float g_s[MTOK * INNER];     // activated state

// ---------------------------------------------------------------------------
// NT SGEMM: C[M,N] = A[M,K] * B[N,K]^T ; A,B row-major.
// If ADD_Z: epilogue adds alpha * emb[ind(row)][col]  (col < INNER).
// Assumes M%BM==0, N%BN==0, K%BK==0 (true for all calls here).
// ---------------------------------------------------------------------------
template <bool ADD_Z>
__global__ __launch_bounds__(256) void sgemm_nt(
    const float* __restrict__ A, const float* __restrict__ Bw,
    float* __restrict__ C, int K, int ldc,
    const float* __restrict__ embi, const int* __restrict__ inds,
    int pred_i, float alpha)
{
    __shared__ float As[BK * AS];
    __shared__ float Bs[BK * AS];

    const int tid = threadIdx.x;
    const int m0 = blockIdx.y * BM;
    const int n0 = blockIdx.x * BN;
    const int tx = tid & 15;          // 0..15  (N direction)
    const int ty = tid >> 4;          // 0..15  (M direction)

    float acc[8][8];
#pragma unroll
    for (int i = 0; i < 8; i++)
#pragma unroll
        for (int j = 0; j < 8; j++) acc[i][j] = 0.0f;

    for (int kt = 0; kt < K; kt += BK) {
        // Load A tile [BM x BK] -> As[k][m], B tile [BN x BK] -> Bs[k][n]
#pragma unroll
        for (int r = 0; r < 2; r++) {
            int idx = tid + r * 256;           // 0..511
            int row = idx >> 2;                // 0..127
            int kq  = (idx & 3) << 2;          // 0,4,8,12
            float4 va = *(const float4*)(A  + (size_t)(m0 + row) * K + kt + kq);
            As[(kq + 0) * AS + row] = va.x;
            As[(kq + 1) * AS + row] = va.y;
            As[(kq + 2) * AS + row] = va.z;
            As[(kq + 3) * AS + row] = va.w;
            float4 vb = *(const float4*)(Bw + (size_t)(n0 + row) * K + kt + kq);
            Bs[(kq + 0) * AS + row] = vb.x;
            Bs[(kq + 1) * AS + row] = vb.y;
            Bs[(kq + 2) * AS + row] = vb.z;
            Bs[(kq + 3) * AS + row] = vb.w;
        }
        __syncthreads();

#pragma unroll
        for (int kk = 0; kk < BK; kk++) {
            float4 a0 = *(const float4*)&As[kk * AS + ty * 8];
            float4 a1 = *(const float4*)&As[kk * AS + ty * 8 + 4];
            float4 b0 = *(const float4*)&Bs[kk * AS + tx * 8];
            float4 b1 = *(const float4*)&Bs[kk * AS + tx * 8 + 4];
            float a[8] = {a0.x, a0.y, a0.z, a0.w, a1.x, a1.y, a1.z, a1.w};
            float b[8] = {b0.x, b0.y, b0.z, b0.w, b1.x, b1.y, b1.z, b1.w};
#pragma unroll
            for (int i = 0; i < 8; i++)
#pragma unroll
                for (int j = 0; j < 8; j++)
                    acc[i][j] = fmaf(a[i], b[j], acc[i][j]);
        }
        __syncthreads();
    }

    // Epilogue
#pragma unroll
    for (int i = 0; i < 8; i++) {
        int m = m0 + ty * 8 + i;
        const float* zrow = nullptr;
        if (ADD_Z) {
            int bb = m >> 9;          // batch
            int nn = m & 511;         // position
            int ind = inds[bb * INDS_LD + pred_i + nn];
            zrow = embi + (size_t)ind * INNER;
        }
        float* crow = C + (size_t)m * ldc + n0 + tx * 8;
#pragma unroll
        for (int j = 0; j < 8; j++) {
            float c = acc[i][j];
            if (ADD_Z) c = fmaf(alpha, zrow[n0 + tx * 8 + j], c);
            crow[j] = c;
        }
    }
}

// ---------------------------------------------------------------------------
// RMS-LN (use_mean=False) + exact GELU, one block per token row (INNER=1024).
// y = gelu( x * rsqrt(mean(x^2)+eps) * w + b )
// ---------------------------------------------------------------------------
__global__ __launch_bounds__(256) void ln_gelu_k(
    const float* __restrict__ X, float* __restrict__ Y,
    const float* __restrict__ w, const float* __restrict__ b)
{
    const int row = blockIdx.x;
    const int tid = threadIdx.x;
    const float4* x4 = (const float4*)(X + (size_t)row * INNER);
    float4 v = x4[tid];
    float ss = v.x * v.x + v.y * v.y + v.z * v.z + v.w * v.w;
#pragma unroll
    for (int o = 16; o > 0; o >>= 1) ss += __shfl_down_sync(0xFFFFFFFFu, ss, o);
    __shared__ float sred[8];
    if ((tid & 31) == 0) sred[tid >> 5] = ss;
    __syncthreads();
    float tot = sred[0] + sred[1] + sred[2] + sred[3] +
                sred[4] + sred[5] + sred[6] + sred[7];
    float rs = rsqrtf(tot * (1.0f / INNER) + 1e-6f);

    int n = tid * 4;
    float4 wv = *(const float4*)(w + n);
    float4 bv = *(const float4*)(b + n);
    float4 o;
    {
        float y = v.x * rs * wv.x + bv.x;
        o.x = 0.5f * y * (1.0f + erff(y * 0.70710678118654752f));
        y = v.y * rs * wv.y + bv.y;
        o.y = 0.5f * y * (1.0f + erff(y * 0.70710678118654752f));
        y = v.z * rs * wv.z + bv.z;
        o.z = 0.5f * y * (1.0f + erff(y * 0.70710678118654752f));
        y = v.w * rs * wv.w + bv.w;
        o.w = 0.5f * y * (1.0f + erff(y * 0.70710678118654752f));
    }
    *(float4*)(Y + (size_t)row * INNER + n) = o;
}

// ---------------------------------------------------------------------------
extern "C" void kernel_launch(void* const* d_in, const int* in_sizes, int n_in,
                              void* d_out, int out_size)
{
    const float* state = (const float*)d_in[0];   // [2, 512, 4096]
    const int*   inds  = (const int*)  d_in[1];   // [2, 515]
    const float* emb   = (const float*)d_in[2];   // [3, 32000, 1024]
    const float* p0    = (const float*)d_in[3];   // [1024, 4096]
    const float* pw    = (const float*)d_in[4];   // [2, 1024, 1024]
    const float* hw    = (const float*)d_in[5];   // [3, 32000, 1024]
    const float* lw    = (const float*)d_in[6];   // [3, 1024]
    const float* lb    = (const float*)d_in[7];   // [3, 1024]
    float* out = (float*)d_out;                   // [3, 2, 512, 32000]

    float *tmp, *s;
    cudaGetSymbolAddress((void**)&tmp, g_tmp);
    cudaGetSymbolAddress((void**)&s,   g_s);

    // ALPHA = sqrt((1 - sw^2) * INNER/2) / sw,  sw = 0.5^(0.5/NPRED)
    double sw = pow(0.5, 0.5 / (double)NPRED);
    float alpha = (float)(sqrt((1.0 - sw * sw) * (INNER / 2.0)) / sw);

    for (int i = 0; i < NPRED; i++) {
        const float* Ain = (i == 0) ? state : s;
        int K = (i == 0) ? EMB_DIM : INNER;
        const float* W = (i == 0) ? p0 : pw + (size_t)(i - 1) * INNER * INNER;

        // proj: tmp = Ain @ W^T + alpha * gather(emb_i)
        sgemm_nt<true><<<dim3(INNER / BN, MTOK / BM), 256>>>(
            Ain, W, tmp, K, INNER,
            emb + (size_t)i * VOCAB * INNER, inds, i, alpha);

        // s = gelu(ln(tmp))
        ln_gelu_k<<<MTOK, 256>>>(tmp, s, lw + i * INNER, lb + i * INNER);

        // logits_i = s @ head_i^T
        sgemm_nt<false><<<dim3(VOCAB / BN, MTOK / BM), 256>>>(
            s, hw + (size_t)i * VOCAB * INNER,
            out + (size_t)i * MTOK * VOCAB, INNER, VOCAB,
            nullptr, nullptr, 0, 0.0f);
    }
}

// round 12
// speedup vs baseline: 1.7454x; 1.7454x over previous
#include <cuda_runtime.h>
#include <cuda_bf16.h>
#include <cstdint>
#include <math.h>

#define EMB_DIM 4096
#define INNER   1024
#define VOCAB   32000
#define NPRED   3
#define BATCH   2
#define SEQ     512
#define MTOK    (BATCH * SEQ)
#define INDS_LD (SEQ + NPRED)

// fp32 SIMT proj tiling
#define BM 128
#define BN 128
#define BK 16
#define AS 132

// head HMMA tiling
#define HBM 128
#define HBN 256
#define HBK 32
#define HBKP 40                       // padded bf16 stride (80B) - conflict-free ldmatrix
#define NIT  96                       // 3 passes x (1024/32)
#define HEAD_SMEM ((2 * HBM * HBKP + 2 * HBN * HBKP) * 2)   // 61440 B

// ---------------- scratch (device globals; no allocation) -------------------
__device__ float g_tmp[MTOK * INNER];
__device__ float g_s[MTOK * INNER];
__device__ __nv_bfloat16 g_Ah[MTOK * INNER];
__device__ __nv_bfloat16 g_Al[MTOK * INNER];
__device__ __nv_bfloat16 g_Bh[(size_t)NPRED * VOCAB * INNER];
__device__ __nv_bfloat16 g_Bl[(size_t)NPRED * VOCAB * INNER];

// ---------------- PTX helpers (sm_80+ features only) ------------------------
__device__ __forceinline__ uint32_t smem_u32(const void* p) {
    uint32_t a;
    asm("{ .reg .u64 t; cvta.to.shared.u64 t, %1; cvt.u32.u64 %0, t; }"
        : "=r"(a) : "l"(p));
    return a;
}
#define CP_ASYNC16(dst, src) \
    asm volatile("cp.async.cg.shared.global [%0], [%1], 16;" \
                 :: "r"(dst), "l"(src))
#define CP_COMMIT() asm volatile("cp.async.commit_group;")
#define CP_WAIT(n)  asm volatile("cp.async.wait_group %0;" :: "n"(n))

#define LDSM4(r, addr) \
    asm volatile("ldmatrix.sync.aligned.m8n8.x4.shared.b16 {%0,%1,%2,%3}, [%4];" \
                 : "=r"((r)[0]), "=r"((r)[1]), "=r"((r)[2]), "=r"((r)[3]) : "r"(addr))

#define MMA16816(d, a, b) \
    asm volatile("mma.sync.aligned.m16n8k16.row.col.f32.bf16.bf16.f32 " \
                 "{%0,%1,%2,%3}, {%4,%5,%6,%7}, {%8,%9}, {%0,%1,%2,%3};" \
                 : "+f"((d)[0]), "+f"((d)[1]), "+f"((d)[2]), "+f"((d)[3]) \
                 : "r"((a)[0]), "r"((a)[1]), "r"((a)[2]), "r"((a)[3]), \
                   "r"((b)[0]), "r"((b)[1]))

// ---------------------------------------------------------------------------
// fp32 SIMT proj GEMM (unchanged from passing baseline)
// ---------------------------------------------------------------------------
template <bool ADD_Z>
__global__ __launch_bounds__(256) void sgemm_nt(
    const float* __restrict__ A, const float* __restrict__ Bw,
    float* __restrict__ C, int K, int ldc,
    const float* __restrict__ embi, const int* __restrict__ inds,
    int pred_i, float alpha)
{
    __shared__ float Asm[BK * AS];
    __shared__ float Bsm[BK * AS];
    const int tid = threadIdx.x;
    const int m0 = blockIdx.y * BM;
    const int n0 = blockIdx.x * BN;
    const int tx = tid & 15, ty = tid >> 4;

    float acc[8][8];
#pragma unroll
    for (int i = 0; i < 8; i++)
#pragma unroll
        for (int j = 0; j < 8; j++) acc[i][j] = 0.0f;

    for (int kt = 0; kt < K; kt += BK) {
#pragma unroll
        for (int r = 0; r < 2; r++) {
            int idx = tid + r * 256;
            int row = idx >> 2;
            int kq = (idx & 3) << 2;
            float4 va = *(const float4*)(A + (size_t)(m0 + row) * K + kt + kq);
            Asm[(kq + 0) * AS + row] = va.x; Asm[(kq + 1) * AS + row] = va.y;
            Asm[(kq + 2) * AS + row] = va.z; Asm[(kq + 3) * AS + row] = va.w;
            float4 vb = *(const float4*)(Bw + (size_t)(n0 + row) * K + kt + kq);
            Bsm[(kq + 0) * AS + row] = vb.x; Bsm[(kq + 1) * AS + row] = vb.y;
            Bsm[(kq + 2) * AS + row] = vb.z; Bsm[(kq + 3) * AS + row] = vb.w;
        }
        __syncthreads();
#pragma unroll
        for (int kk = 0; kk < BK; kk++) {
            float4 a0 = *(const float4*)&Asm[kk * AS + ty * 8];
            float4 a1 = *(const float4*)&Asm[kk * AS + ty * 8 + 4];
            float4 b0 = *(const float4*)&Bsm[kk * AS + tx * 8];
            float4 b1 = *(const float4*)&Bsm[kk * AS + tx * 8 + 4];
            float a[8] = {a0.x,a0.y,a0.z,a0.w,a1.x,a1.y,a1.z,a1.w};
            float b[8] = {b0.x,b0.y,b0.z,b0.w,b1.x,b1.y,b1.z,b1.w};
#pragma unroll
            for (int i = 0; i < 8; i++)
#pragma unroll
                for (int j = 0; j < 8; j++) acc[i][j] = fmaf(a[i], b[j], acc[i][j]);
        }
        __syncthreads();
    }
#pragma unroll
    for (int i = 0; i < 8; i++) {
        int m = m0 + ty * 8 + i;
        const float* zrow = nullptr;
        if (ADD_Z) {
            int bb = m >> 9, nn = m & 511;
            int ind = inds[bb * INDS_LD + pred_i + nn];
            zrow = embi + (size_t)ind * INNER;
        }
        float* crow = C + (size_t)m * ldc + n0 + tx * 8;
#pragma unroll
        for (int j = 0; j < 8; j++) {
            float c = acc[i][j];
            if (ADD_Z) c = fmaf(alpha, zrow[n0 + tx * 8 + j], c);
            crow[j] = c;
        }
    }
}

// ---------------------------------------------------------------------------
// RMS-LN + exact GELU; emits fp32 s (for next proj) AND bf16 hi/lo split
// ---------------------------------------------------------------------------
__global__ __launch_bounds__(256) void ln_gelu_k(
    const float* __restrict__ X, float* __restrict__ Y,
    __nv_bfloat16* __restrict__ Yh, __nv_bfloat16* __restrict__ Yl,
    const float* __restrict__ w, const float* __restrict__ b)
{
    const int row = blockIdx.x;
    const int tid = threadIdx.x;
    const float4* x4 = (const float4*)(X + (size_t)row * INNER);
    float4 v = x4[tid];
    float ss = v.x*v.x + v.y*v.y + v.z*v.z + v.w*v.w;
#pragma unroll
    for (int o = 16; o > 0; o >>= 1) ss += __shfl_down_sync(0xFFFFFFFFu, ss, o);
    __shared__ float sred[8];
    if ((tid & 31) == 0) sred[tid >> 5] = ss;
    __syncthreads();
    float tot = sred[0]+sred[1]+sred[2]+sred[3]+sred[4]+sred[5]+sred[6]+sred[7];
    float rs = rsqrtf(tot * (1.0f / INNER) + 1e-6f);

    int n = tid * 4;
    float4 wv = *(const float4*)(w + n);
    float4 bv = *(const float4*)(b + n);
    float4 o;
    float y;
    y = v.x*rs*wv.x + bv.x; o.x = 0.5f*y*(1.0f+erff(y*0.70710678118654752f));
    y = v.y*rs*wv.y + bv.y; o.y = 0.5f*y*(1.0f+erff(y*0.70710678118654752f));
    y = v.z*rs*wv.z + bv.z; o.z = 0.5f*y*(1.0f+erff(y*0.70710678118654752f));
    y = v.w*rs*wv.w + bv.w; o.w = 0.5f*y*(1.0f+erff(y*0.70710678118654752f));
    *(float4*)(Y + (size_t)row * INNER + n) = o;

    union { __nv_bfloat16 h[4]; uint2 u; } ph, pl;
    float f[4] = {o.x, o.y, o.z, o.w};
#pragma unroll
    for (int j = 0; j < 4; j++) {
        __nv_bfloat16 hh = __float2bfloat16(f[j]);
        ph.h[j] = hh;
        pl.h[j] = __float2bfloat16(f[j] - __bfloat162float(hh));
    }
    *(uint2*)(Yh + (size_t)row * INNER + n) = ph.u;
    *(uint2*)(Yl + (size_t)row * INNER + n) = pl.u;
}

// ---------------------------------------------------------------------------
// Split head weights fp32 -> bf16 hi/lo (all 3 preds)
// ---------------------------------------------------------------------------
__global__ __launch_bounds__(256) void pack_b_k(
    const float* __restrict__ W, __nv_bfloat16* __restrict__ Wh,
    __nv_bfloat16* __restrict__ Wl)
{
    size_t i = (size_t)blockIdx.x * 256 + threadIdx.x;   // float4 group index
    float4 v = *(const float4*)(W + i * 4);
    union { __nv_bfloat16 h[4]; uint2 u; } ph, pl;
    float f[4] = {v.x, v.y, v.z, v.w};
#pragma unroll
    for (int j = 0; j < 4; j++) {
        __nv_bfloat16 hh = __float2bfloat16(f[j]);
        ph.h[j] = hh;
        pl.h[j] = __float2bfloat16(f[j] - __bfloat162float(hh));
    }
    *(uint2*)(Wh + i * 4) = ph.u;
    *(uint2*)(Wl + i * 4) = pl.u;
}

// ---------------------------------------------------------------------------
// head GEMM via mma.sync (HMMA bf16, fp32 accum), 3-pass bf16 split.
// C[1024,32000] = A[1024,1024] @ B[32000,1024]^T
// CTA 128x256, BK=32, 8 warps (warp tile 64x64), cp.async double buffer.
// ---------------------------------------------------------------------------
__global__ __launch_bounds__(256) void head_gemm(
    const __nv_bfloat16* __restrict__ Ah, const __nv_bfloat16* __restrict__ Al,
    const __nv_bfloat16* __restrict__ Bh, const __nv_bfloat16* __restrict__ Bl,
    float* __restrict__ C)
{
    extern __shared__ __nv_bfloat16 sh[];
    __nv_bfloat16* As = sh;                         // [2][HBM*HBKP]
    __nv_bfloat16* Bs = sh + 2 * HBM * HBKP;        // [2][HBN*HBKP]
    const uint32_t sA = smem_u32(As);
    const uint32_t sB = smem_u32(Bs);

    const int tid = threadIdx.x;
    const int wid = tid >> 5;
    const int lane = tid & 31;
    const int m0 = blockIdx.y * HBM;
    const int n0 = blockIdx.x * HBN;
    const int wm = (wid & 1) * 64;                  // warp M offset
    const int wn = (wid >> 1) * 64;                 // warp N offset

    float d[4][8][4];
#pragma unroll
    for (int i = 0; i < 4; i++)
#pragma unroll
        for (int j = 0; j < 8; j++)
#pragma unroll
            for (int k = 0; k < 4; k++) d[i][j][k] = 0.0f;

    // ldmatrix source addresses (per-lane constants modulo stage/k16 offset)
    const int a_row = (lane & 15);
    const int a_k   = (lane >> 4) * 8;
    const int b_row = (lane & 7) + ((lane & 16) ? 8 : 0);
    const int b_k   = (lane & 8) ? 8 : 0;

#define LOAD_STAGE(s, it) do {                                                \
    int _p = (it) >> 5;                                                       \
    int _kt = ((it) & 31) * HBK;                                              \
    const __nv_bfloat16* _Ap = (_p == 1) ? Al : Ah;                           \
    const __nv_bfloat16* _Bp = (_p == 2) ? Bl : Bh;                           \
    _Pragma("unroll")                                                         \
    for (int _i = 0; _i < 2; _i++) {                                          \
        int _idx = tid + _i * 256;                                            \
        int _row = _idx >> 2, _ch = _idx & 3;                                 \
        uint32_t _dst = sA + ((s) * HBM * HBKP + _row * HBKP + _ch * 8) * 2;  \
        const __nv_bfloat16* _src = _Ap + (size_t)(m0 + _row) * INNER + _kt + _ch * 8; \
        CP_ASYNC16(_dst, _src);                                               \
    }                                                                         \
    _Pragma("unroll")                                                         \
    for (int _i = 0; _i < 4; _i++) {                                          \
        int _idx = tid + _i * 256;                                            \
        int _row = _idx >> 2, _ch = _idx & 3;                                 \
        uint32_t _dst = sB + ((s) * HBN * HBKP + _row * HBKP + _ch * 8) * 2;  \
        const __nv_bfloat16* _src = _Bp + (size_t)(n0 + _row) * INNER + _kt + _ch * 8; \
        CP_ASYNC16(_dst, _src);                                               \
    }                                                                         \
    CP_COMMIT();                                                              \
} while (0)

    LOAD_STAGE(0, 0);

    for (int it = 0; it < NIT; it++) {
        const int s = it & 1;
        if (it + 1 < NIT) {
            LOAD_STAGE((it + 1) & 1, it + 1);
            CP_WAIT(1);
        } else {
            CP_WAIT(0);
        }
        __syncthreads();

        const uint32_t baseA = sA + (s * HBM * HBKP) * 2;
        const uint32_t baseB = sB + (s * HBN * HBKP) * 2;
#pragma unroll
        for (int ks = 0; ks < 2; ks++) {
            const int k16 = ks * 16;
            uint32_t a[4][4];
#pragma unroll
            for (int mt = 0; mt < 4; mt++) {
                uint32_t addr = baseA +
                    ((wm + mt * 16 + a_row) * HBKP + k16 + a_k) * 2;
                LDSM4(a[mt], addr);
            }
            uint32_t b[8][2];
#pragma unroll
            for (int nt = 0; nt < 4; nt++) {
                uint32_t r4[4];
                uint32_t addr = baseB +
                    ((wn + nt * 16 + b_row) * HBKP + k16 + b_k) * 2;
                LDSM4(r4, addr);
                b[2 * nt][0] = r4[0]; b[2 * nt][1] = r4[1];
                b[2 * nt + 1][0] = r4[2]; b[2 * nt + 1][1] = r4[3];
            }
#pragma unroll
            for (int mt = 0; mt < 4; mt++)
#pragma unroll
                for (int nt = 0; nt < 8; nt++)
                    MMA16816(d[mt][nt], a[mt], b[nt]);
        }
        __syncthreads();
    }

    // epilogue
#pragma unroll
    for (int mt = 0; mt < 4; mt++) {
        int row = m0 + wm + mt * 16 + (lane >> 2);
#pragma unroll
        for (int nt = 0; nt < 8; nt++) {
            int col = n0 + wn + nt * 8 + 2 * (lane & 3);
            float2 v0 = make_float2(d[mt][nt][0], d[mt][nt][1]);
            float2 v1 = make_float2(d[mt][nt][2], d[mt][nt][3]);
            *(float2*)(C + (size_t)row * VOCAB + col) = v0;
            *(float2*)(C + (size_t)(row + 8) * VOCAB + col) = v1;
        }
    }
#undef LOAD_STAGE
}

// ---------------------------------------------------------------------------
extern "C" void kernel_launch(void* const* d_in, const int* in_sizes, int n_in,
                              void* d_out, int out_size)
{
    const float* state = (const float*)d_in[0];
    const int*   inds  = (const int*)  d_in[1];
    const float* emb   = (const float*)d_in[2];
    const float* p0    = (const float*)d_in[3];
    const float* pw    = (const float*)d_in[4];
    const float* hw    = (const float*)d_in[5];
    const float* lw    = (const float*)d_in[6];
    const float* lb    = (const float*)d_in[7];
    float* out = (float*)d_out;

    float *tmp, *s;
    __nv_bfloat16 *ah, *al, *bh, *bl;
    cudaGetSymbolAddress((void**)&tmp, g_tmp);
    cudaGetSymbolAddress((void**)&s,   g_s);
    cudaGetSymbolAddress((void**)&ah,  g_Ah);
    cudaGetSymbolAddress((void**)&al,  g_Al);
    cudaGetSymbolAddress((void**)&bh,  g_Bh);
    cudaGetSymbolAddress((void**)&bl,  g_Bl);

    cudaFuncSetAttribute(head_gemm,
        cudaFuncAttributeMaxDynamicSharedMemorySize, HEAD_SMEM);

    double sw = pow(0.5, 0.5 / (double)NPRED);
    float alpha = (float)(sqrt((1.0 - sw * sw) * (INNER / 2.0)) / sw);

    // split all head weights once per launch
    {
        size_t groups = (size_t)NPRED * VOCAB * INNER / 4;   // 24,576,000
        pack_b_k<<<(unsigned)(groups / 256), 256>>>(hw, bh, bl);
    }

    for (int i = 0; i < NPRED; i++) {
        const float* Ain = (i == 0) ? state : s;
        int K = (i == 0) ? EMB_DIM : INNER;
        const float* W = (i == 0) ? p0 : pw + (size_t)(i - 1) * INNER * INNER;

        sgemm_nt<true><<<dim3(INNER / BN, MTOK / BM), 256>>>(
            Ain, W, tmp, K, INNER,
            emb + (size_t)i * VOCAB * INNER, inds, i, alpha);

        ln_gelu_k<<<MTOK, 256>>>(tmp, s, ah, al, lw + i * INNER, lb + i * INNER);

        head_gemm<<<dim3(VOCAB / HBN, MTOK / HBM), 256, HEAD_SMEM>>>(
            ah, al,
            bh + (size_t)i * VOCAB * INNER, bl + (size_t)i * VOCAB * INNER,
            out + (size_t)i * MTOK * VOCAB);
    }
}